// round 14
// baseline (speedup 1.0000x reference)
#include <cuda_runtime.h>
#include <cuda_bf16.h>
#include <cuda_fp16.h>
#include <mma.h>

#define N_NODES 100000
#define D 128
#define N_EDGES 1600000
#define BATCH 500000
#define LN_EPS 1e-5f
#define SCAN_CHUNK 1024
#define NBLK ((N_NODES + SCAN_CHUNK - 1) / SCAN_CHUNK)   // 98

using namespace nvcuda;

// Scratch (device globals; no allocation allowed)
__device__ __align__(128) __half g_h1h[N_NODES * D]; // GEMM output (fp16)
__device__ __align__(128) int2  g_epack[N_EDGES];    // CSR-permuted {col, val}
__device__ int g_eloc[N_EDGES];
__device__ int g_elocb[BATCH];
__device__ int g_bidx[BATCH];                        // batch ids grouped by node
__device__ int g_cnt[N_NODES];
__device__ int g_cntb[N_NODES];
__device__ int g_rowptr[N_NODES + 1];
__device__ int g_rowptrb[N_NODES + 1];
__device__ int g_pub0[NBLK];                         // published block totals (-1 = empty)
__device__ int g_pub1[NBLK];
__device__ __align__(128) __nv_bfloat16 g_Wh[D * D];
__device__ __align__(128) __nv_bfloat16 g_Wl[D * D];

#define LDA 136
#define LDB 136
#define LDC 132
#define BLK_ROWS 64
#define GEMM_SMEM (128 * LDB * 2 * 2 + BLK_ROWS * LDA * 2 * 2)   // 104448

// ---------------- init: W hi/lo pre-conversion + zero counters + scan flags ----------
__global__ void init_kernel(const float* __restrict__ W) {
    int i = blockIdx.x * blockDim.x + threadIdx.x;
    if (i < D * D) {
        float wv = W[i];
        __nv_bfloat16 whi = __float2bfloat16(wv);
        g_Wh[i] = whi;
        g_Wl[i] = __float2bfloat16(wv - __bfloat162float(whi));
    }
    if (i < N_NODES) { g_cnt[i] = 0; g_cntb[i] = 0; }
    if (i < NBLK) { g_pub0[i] = -1; g_pub1[i] = -1; }
}

// ---------------- GEMM: h1 = emb @ W + bias (bf16 hi/lo, fp32 accum, fp16 store) ------
__global__ void gemm_kernel(const float* __restrict__ emb,
                            const float* __restrict__ bias) {
    extern __shared__ __nv_bfloat16 smem[];
    __nv_bfloat16* sWh = smem;
    __nv_bfloat16* sWl = sWh + 128 * LDB;
    __nv_bfloat16* sAh = sWl + 128 * LDB;
    __nv_bfloat16* sAl = sAh + BLK_ROWS * LDA;
    float* sC = (float*)sAh;

    int tid = threadIdx.x;
    int wid = tid >> 5;
    int wr = wid >> 1;
    int wc = wid & 1;
    int block_row = blockIdx.x * BLK_ROWS;

    for (int i = tid; i < 128 * 16; i += 256) {
        int r = i >> 4, q = i & 15;
        ((uint4*)(sWh + r * LDB))[q] = ((const uint4*)(g_Wh + r * D))[q];
        ((uint4*)(sWl + r * LDB))[q] = ((const uint4*)(g_Wl + r * D))[q];
    }
    for (int i = tid; i < BLK_ROWS * 32; i += 256) {
        int r = i >> 5, c4 = i & 31;
        int grow = block_row + r;
        float4 a = make_float4(0.f, 0.f, 0.f, 0.f);
        if (grow < N_NODES) a = ((const float4*)(emb + (size_t)grow * D))[c4];
        __nv_bfloat16 h0 = __float2bfloat16(a.x), h1 = __float2bfloat16(a.y);
        __nv_bfloat16 h2 = __float2bfloat16(a.z), h3 = __float2bfloat16(a.w);
        __nv_bfloat16 l0 = __float2bfloat16(a.x - __bfloat162float(h0));
        __nv_bfloat16 l1 = __float2bfloat16(a.y - __bfloat162float(h1));
        __nv_bfloat16 l2 = __float2bfloat16(a.z - __bfloat162float(h2));
        __nv_bfloat16 l3 = __float2bfloat16(a.w - __bfloat162float(h3));
        __nv_bfloat162* ph = (__nv_bfloat162*)(sAh + r * LDA);
        __nv_bfloat162* pl = (__nv_bfloat162*)(sAl + r * LDA);
        ph[c4 * 2]     = __nv_bfloat162(h0, h1);
        ph[c4 * 2 + 1] = __nv_bfloat162(h2, h3);
        pl[c4 * 2]     = __nv_bfloat162(l0, l1);
        pl[c4 * 2 + 1] = __nv_bfloat162(l2, l3);
    }
    __syncthreads();

    wmma::fragment<wmma::accumulator, 16, 16, 16, float> acc[4];
    #pragma unroll
    for (int c = 0; c < 4; c++) wmma::fill_fragment(acc[c], 0.f);

    #pragma unroll
    for (int k = 0; k < 8; k++) {
        wmma::fragment<wmma::matrix_a, 16, 16, 16, __nv_bfloat16, wmma::row_major> ah, al;
        wmma::load_matrix_sync(ah, sAh + wr * 16 * LDA + k * 16, LDA);
        wmma::load_matrix_sync(al, sAl + wr * 16 * LDA + k * 16, LDA);
        #pragma unroll
        for (int c = 0; c < 4; c++) {
            int cc = wc * 64 + c * 16;
            wmma::fragment<wmma::matrix_b, 16, 16, 16, __nv_bfloat16, wmma::row_major> bh, bl;
            wmma::load_matrix_sync(bh, sWh + k * 16 * LDB + cc, LDB);
            wmma::load_matrix_sync(bl, sWl + k * 16 * LDB + cc, LDB);
            wmma::mma_sync(acc[c], ah, bh, acc[c]);
            wmma::mma_sync(acc[c], ah, bl, acc[c]);
            wmma::mma_sync(acc[c], al, bh, acc[c]);
        }
    }
    __syncthreads();
    #pragma unroll
    for (int c = 0; c < 4; c++)
        wmma::store_matrix_sync(sC + wr * 16 * LDC + wc * 64 + c * 16, acc[c],
                                LDC, wmma::mem_row_major);
    __syncthreads();

    for (int i = tid; i < BLK_ROWS * 32; i += 256) {
        int r = i >> 5, c4 = i & 31;
        int grow = block_row + r;
        if (grow < N_NODES) {
            float4 cv = ((const float4*)(sC + r * LDC))[c4];
            float4 bv = ((const float4*)bias)[c4];
            __half2* p = (__half2*)(g_h1h + (size_t)grow * D);
            p[c4 * 2]     = __floats2half2_rn(cv.x + bv.x, cv.y + bv.y);
            p[c4 * 2 + 1] = __floats2half2_rn(cv.z + bv.z, cv.w + bv.w);
        }
    }
}

// ---------------- dual histogram: edges then batch (one atomic pass) ----------------
__global__ void hist_kernel(const int* __restrict__ rows, const int* __restrict__ x) {
    int i = blockIdx.x * blockDim.x + threadIdx.x;
    if (i < N_EDGES) g_eloc[i] = atomicAdd(&g_cnt[rows[i]], 1);
    int b = i - N_EDGES;
    if (b >= 0 && b < BATCH) {
        int xv = x[b];
        if (xv >= 1 && xv <= N_NODES) g_elocb[b] = atomicAdd(&g_cntb[xv - 1], 1);
        else g_elocb[b] = -1;
    }
}

// ---------------- fused single-pass scan (publish + lookback) ----------------
// Grid (NBLK, 2) = 196 blocks @ 1024 thr -> all resident in wave 1 -> spin is safe.
__global__ void scan_kernel() {
    __shared__ int ws[32];
    __shared__ int sadd;
    int a = blockIdx.y;
    const int* cnt = a ? g_cntb : g_cnt;
    int* rp = a ? g_rowptrb : g_rowptr;
    int* pub = a ? g_pub1 : g_pub0;
    int tid = threadIdx.x;
    int lane = tid & 31, w = tid >> 5;
    int idx = blockIdx.x * SCAN_CHUNK + tid;
    int v = (idx < N_NODES) ? cnt[idx] : 0;
    int inc = v;
    #pragma unroll
    for (int off = 1; off < 32; off <<= 1) {
        int t = __shfl_up_sync(0xffffffffu, inc, off);
        if (lane >= off) inc += t;
    }
    if (lane == 31) ws[w] = inc;
    __syncthreads();
    if (w == 0) {
        int b = ws[lane];
        #pragma unroll
        for (int off = 1; off < 32; off <<= 1) {
            int t = __shfl_up_sync(0xffffffffu, b, off);
            if (lane >= off) b += t;
        }
        ws[lane] = b;
    }
    if (tid == 0) sadd = 0;
    __syncthreads();
    int total_prefix = inc + (w ? ws[w - 1] : 0);
    if (tid == 0) atomicExch(&pub[blockIdx.x], ws[31]);   // publish block total

    // lookback: thread t < blockIdx.x spins on predecessor t's total
    int add = 0;
    if (tid < blockIdx.x) {
        volatile int* p = (volatile int*)&pub[tid];
        int pv;
        do { pv = *p; } while (pv < 0);
        add = pv;
    }
    #pragma unroll
    for (int off = 16; off; off >>= 1) add += __shfl_xor_sync(0xffffffffu, add, off);
    if (lane == 0 && add) atomicAdd(&sadd, add);
    __syncthreads();
    int offset = sadd;
    if (idx < N_NODES) rp[idx + 1] = total_prefix + offset;
    if (idx == 0) rp[0] = 0;
}

// ---------------- fused scatter: edges + batch ids (+ zero invalid out rows) ----------
__global__ void scatter_kernel(const float* __restrict__ vals,
                               const int* __restrict__ rows,
                               const int* __restrict__ cols,
                               const int* __restrict__ x,
                               float* __restrict__ out) {
    int i = blockIdx.x * blockDim.x + threadIdx.x;
    if (i < N_EDGES) {
        int p = g_rowptr[rows[i]] + g_eloc[i];
        g_epack[p] = make_int2(cols[i], __float_as_int(vals[i]));
    }
    int b = i - N_EDGES;
    if (b >= 0 && b < BATCH) {
        int xv = x[b];
        if (xv >= 1 && xv <= N_NODES) {
            g_bidx[g_rowptrb[xv - 1] + g_elocb[b]] = b;
        } else {
            float4* o = (float4*)(out + (size_t)b * D);
            #pragma unroll
            for (int k = 0; k < 32; k++) o[k] = make_float4(0.f, 0.f, 0.f, 0.f);
        }
    }
}

// ---------------- fused SpMM + ReLU + LayerNorm + direct batch scatter ----------------
// Half-warp scheme: lanes [0,16) and [16,32) process DIFFERENT edges of a pair;
// each lane loads uint4 (8 features, 16B). Halves combined via shfl_xor(16) before LN.
__global__ void spmm_ln_kernel(const float* __restrict__ gamma,
                               const float* __restrict__ beta,
                               float* __restrict__ out) {
    int row = blockIdx.x * 8 + (threadIdx.x >> 5);
    if (row >= N_NODES) return;
    int lane = threadIdx.x & 31;
    int sub = lane & 15;
    int h = lane >> 4;
    int s = g_rowptr[row];
    int e = g_rowptr[row + 1];

    float acc[8];
    #pragma unroll
    for (int i = 0; i < 8; i++) acc[i] = 0.f;

    for (int base = s; base < e; base += 32) {
        int n = min(32, e - base);
        int2 ev = make_int2(0, 0);
        if (base + lane < e) ev = g_epack[base + lane];   // lanes >= n hold {0,0}
        int pairs = (n + 1) >> 1;
        int p = 0;
        for (; p + 4 <= pairs; p += 4) {
            float v[4]; uint4 m[4];
            #pragma unroll
            for (int u = 0; u < 4; u++) {
                int src = 2 * (p + u) + h;
                int c = __shfl_sync(0xffffffffu, ev.x, src);
                v[u] = __int_as_float(__shfl_sync(0xffffffffu, ev.y, src));
                m[u] = ((const uint4*)(g_h1h + (size_t)c * D))[sub];
            }
            #pragma unroll
            for (int u = 0; u < 4; u++) {
                float2 f0 = __half22float2(*(__half2*)&m[u].x);
                float2 f1 = __half22float2(*(__half2*)&m[u].y);
                float2 f2 = __half22float2(*(__half2*)&m[u].z);
                float2 f3 = __half22float2(*(__half2*)&m[u].w);
                acc[0] = fmaf(v[u], f0.x, acc[0]);
                acc[1] = fmaf(v[u], f0.y, acc[1]);
                acc[2] = fmaf(v[u], f1.x, acc[2]);
                acc[3] = fmaf(v[u], f1.y, acc[3]);
                acc[4] = fmaf(v[u], f2.x, acc[4]);
                acc[5] = fmaf(v[u], f2.y, acc[5]);
                acc[6] = fmaf(v[u], f3.x, acc[6]);
                acc[7] = fmaf(v[u], f3.y, acc[7]);
            }
        }
        for (; p < pairs; p++) {
            int src = 2 * p + h;
            int c = __shfl_sync(0xffffffffu, ev.x, src);
            float v = __int_as_float(__shfl_sync(0xffffffffu, ev.y, src));
            uint4 m = ((const uint4*)(g_h1h + (size_t)c * D))[sub];
            float2 f0 = __half22float2(*(__half2*)&m.x);
            float2 f1 = __half22float2(*(__half2*)&m.y);
            float2 f2 = __half22float2(*(__half2*)&m.z);
            float2 f3 = __half22float2(*(__half2*)&m.w);
            acc[0] = fmaf(v, f0.x, acc[0]);
            acc[1] = fmaf(v, f0.y, acc[1]);
            acc[2] = fmaf(v, f1.x, acc[2]);
            acc[3] = fmaf(v, f1.y, acc[3]);
            acc[4] = fmaf(v, f2.x, acc[4]);
            acc[5] = fmaf(v, f2.y, acc[5]);
            acc[6] = fmaf(v, f3.x, acc[6]);
            acc[7] = fmaf(v, f3.y, acc[7]);
        }
    }

    // combine the two edge halves (lane sub and sub+16 then hold identical sums)
    #pragma unroll
    for (int i = 0; i < 8; i++) acc[i] += __shfl_xor_sync(0xffffffffu, acc[i], 16);

    // relu
    #pragma unroll
    for (int i = 0; i < 8; i++) acc[i] = fmaxf(acc[i], 0.f);

    // layernorm over 128 (reduce over the 16 distinct sub-lanes only)
    float sm = 0.f;
    #pragma unroll
    for (int i = 0; i < 8; i++) sm += acc[i];
    #pragma unroll
    for (int off = 8; off; off >>= 1) sm += __shfl_xor_sync(0xffffffffu, sm, off);
    float mu = sm * (1.f / 128.f);

    float d[8]; float q = 0.f;
    #pragma unroll
    for (int i = 0; i < 8; i++) { d[i] = acc[i] - mu; q = fmaf(d[i], d[i], q); }
    #pragma unroll
    for (int off = 8; off; off >>= 1) q += __shfl_xor_sync(0xffffffffu, q, off);
    float rs = rsqrtf(q * (1.f / 128.f) + LN_EPS);

    float4 g0 = ((const float4*)gamma)[2 * sub];
    float4 g1 = ((const float4*)gamma)[2 * sub + 1];
    float4 b0 = ((const float4*)beta)[2 * sub];
    float4 b1 = ((const float4*)beta)[2 * sub + 1];
    float4 o0, o1;
    o0.x = d[0] * rs * g0.x + b0.x;
    o0.y = d[1] * rs * g0.y + b0.y;
    o0.z = d[2] * rs * g0.z + b0.z;
    o0.w = d[3] * rs * g0.w + b0.w;
    o1.x = d[4] * rs * g1.x + b1.x;
    o1.y = d[5] * rs * g1.y + b1.y;
    o1.z = d[6] * rs * g1.z + b1.z;
    o1.w = d[7] * rs * g1.w + b1.w;

    // direct scatter; the two halves split the target list
    int sb = g_rowptrb[row];
    int eb = g_rowptrb[row + 1];
    for (int t = sb + h; t < eb; t += 2) {
        int b2 = g_bidx[t];
        float4* dst = (float4*)(out + (size_t)b2 * D);
        __stcs(dst + 2 * sub, o0);
        __stcs(dst + 2 * sub + 1, o1);
    }
}

extern "C" void kernel_launch(void* const* d_in, const int* in_sizes, int n_in,
                              void* d_out, int out_size) {
    const int*   x     = (const int*)d_in[0];
    const float* emb   = (const float*)d_in[1];
    const float* W     = (const float*)d_in[2];
    const float* bias  = (const float*)d_in[3];
    const float* vals  = (const float*)d_in[4];
    const int*   rows  = (const int*)d_in[5];
    const int*   cols  = (const int*)d_in[6];
    const float* gamma = (const float*)d_in[7];
    const float* beta  = (const float*)d_in[8];
    float* out = (float*)d_out;

    static cudaStream_t s2 = nullptr;
    static cudaEvent_t evFork = nullptr, evJoin = nullptr;
    if (s2 == nullptr) {
        cudaStreamCreateWithFlags(&s2, cudaStreamNonBlocking);
        cudaEventCreateWithFlags(&evFork, cudaEventDisableTiming);
        cudaEventCreateWithFlags(&evJoin, cudaEventDisableTiming);
    }

    cudaFuncSetAttribute(gemm_kernel, cudaFuncAttributeMaxDynamicSharedMemorySize, GEMM_SMEM);

    // init feeds both branches (W for gemm, zeroed counters + scan flags for CSR)
    init_kernel<<<(N_NODES + 255) / 256, 256>>>(W);

    // fork: CSR chain on s2 overlaps GEMM on the main stream
    cudaEventRecord(evFork, 0);
    cudaStreamWaitEvent(s2, evFork, 0);

    hist_kernel<<<(N_EDGES + BATCH + 255) / 256, 256, 0, s2>>>(rows, x);
    scan_kernel<<<dim3(NBLK, 2), SCAN_CHUNK, 0, s2>>>();
    scatter_kernel<<<(N_EDGES + BATCH + 255) / 256, 256, 0, s2>>>(vals, rows, cols, x, out);

    gemm_kernel<<<(N_NODES + BLK_ROWS - 1) / BLK_ROWS, 256, GEMM_SMEM>>>(emb, bias);

    // join
    cudaEventRecord(evJoin, s2);
    cudaStreamWaitEvent(0, evJoin, 0);

    spmm_ln_kernel<<<(N_NODES + 7) / 8, 256>>>(gamma, beta, out);
}

// round 16
// speedup vs baseline: 1.0443x; 1.0443x over previous
#include <cuda_runtime.h>
#include <cuda_bf16.h>
#include <cuda_fp16.h>
#include <mma.h>

#define N_NODES 100000
#define D 128
#define N_EDGES 1600000
#define BATCH 500000
#define LN_EPS 1e-5f
#define SCAN_CHUNK 1024
#define NBLK ((N_NODES + SCAN_CHUNK - 1) / SCAN_CHUNK)   // 98

using namespace nvcuda;

// Scratch (device globals; no allocation allowed)
__device__ __align__(128) __half g_h1h[N_NODES * D]; // GEMM output (fp16)
__device__ __align__(128) int2  g_epack[N_EDGES];    // CSR-permuted {col, val}
__device__ int g_eloc[N_EDGES];
__device__ int g_elocb[BATCH];
__device__ int g_bidx[BATCH];                        // batch ids grouped by node
__device__ int g_cnt[N_NODES];
__device__ int g_cntb[N_NODES];
__device__ int g_rowptr[N_NODES + 1];
__device__ int g_rowptrb[N_NODES + 1];
__device__ int g_pub0[NBLK];                         // published block totals (-1 = empty)
__device__ int g_pub1[NBLK];
__device__ __align__(128) __nv_bfloat16 g_Wh[D * D];
__device__ __align__(128) __nv_bfloat16 g_Wl[D * D];

#define LDA 136
#define LDB 136
#define LDC 132
#define BLK_ROWS 64
#define GEMM_SMEM (128 * LDB * 2 * 2 + BLK_ROWS * LDA * 2 * 2)   // 104448

// ---------------- init: W hi/lo pre-conversion + zero counters + scan flags ----------
__global__ void init_kernel(const float* __restrict__ W) {
    int i = blockIdx.x * blockDim.x + threadIdx.x;
    if (i < D * D) {
        float wv = W[i];
        __nv_bfloat16 whi = __float2bfloat16(wv);
        g_Wh[i] = whi;
        g_Wl[i] = __float2bfloat16(wv - __bfloat162float(whi));
    }
    if (i < N_NODES) { g_cnt[i] = 0; g_cntb[i] = 0; }
    if (i < NBLK) { g_pub0[i] = -1; g_pub1[i] = -1; }
}

// ---------------- GEMM: h1 = emb @ W + bias (bf16 hi/lo, fp32 accum, fp16 store) ------
__global__ void gemm_kernel(const float* __restrict__ emb,
                            const float* __restrict__ bias) {
    extern __shared__ __nv_bfloat16 smem[];
    __nv_bfloat16* sWh = smem;
    __nv_bfloat16* sWl = sWh + 128 * LDB;
    __nv_bfloat16* sAh = sWl + 128 * LDB;
    __nv_bfloat16* sAl = sAh + BLK_ROWS * LDA;
    float* sC = (float*)sAh;

    int tid = threadIdx.x;
    int wid = tid >> 5;
    int wr = wid >> 1;
    int wc = wid & 1;
    int block_row = blockIdx.x * BLK_ROWS;

    for (int i = tid; i < 128 * 16; i += 256) {
        int r = i >> 4, q = i & 15;
        ((uint4*)(sWh + r * LDB))[q] = ((const uint4*)(g_Wh + r * D))[q];
        ((uint4*)(sWl + r * LDB))[q] = ((const uint4*)(g_Wl + r * D))[q];
    }
    for (int i = tid; i < BLK_ROWS * 32; i += 256) {
        int r = i >> 5, c4 = i & 31;
        int grow = block_row + r;
        float4 a = make_float4(0.f, 0.f, 0.f, 0.f);
        if (grow < N_NODES) a = ((const float4*)(emb + (size_t)grow * D))[c4];
        __nv_bfloat16 h0 = __float2bfloat16(a.x), h1 = __float2bfloat16(a.y);
        __nv_bfloat16 h2 = __float2bfloat16(a.z), h3 = __float2bfloat16(a.w);
        __nv_bfloat16 l0 = __float2bfloat16(a.x - __bfloat162float(h0));
        __nv_bfloat16 l1 = __float2bfloat16(a.y - __bfloat162float(h1));
        __nv_bfloat16 l2 = __float2bfloat16(a.z - __bfloat162float(h2));
        __nv_bfloat16 l3 = __float2bfloat16(a.w - __bfloat162float(h3));
        __nv_bfloat162* ph = (__nv_bfloat162*)(sAh + r * LDA);
        __nv_bfloat162* pl = (__nv_bfloat162*)(sAl + r * LDA);
        ph[c4 * 2]     = __nv_bfloat162(h0, h1);
        ph[c4 * 2 + 1] = __nv_bfloat162(h2, h3);
        pl[c4 * 2]     = __nv_bfloat162(l0, l1);
        pl[c4 * 2 + 1] = __nv_bfloat162(l2, l3);
    }
    __syncthreads();

    wmma::fragment<wmma::accumulator, 16, 16, 16, float> acc[4];
    #pragma unroll
    for (int c = 0; c < 4; c++) wmma::fill_fragment(acc[c], 0.f);

    #pragma unroll
    for (int k = 0; k < 8; k++) {
        wmma::fragment<wmma::matrix_a, 16, 16, 16, __nv_bfloat16, wmma::row_major> ah, al;
        wmma::load_matrix_sync(ah, sAh + wr * 16 * LDA + k * 16, LDA);
        wmma::load_matrix_sync(al, sAl + wr * 16 * LDA + k * 16, LDA);
        #pragma unroll
        for (int c = 0; c < 4; c++) {
            int cc = wc * 64 + c * 16;
            wmma::fragment<wmma::matrix_b, 16, 16, 16, __nv_bfloat16, wmma::row_major> bh, bl;
            wmma::load_matrix_sync(bh, sWh + k * 16 * LDB + cc, LDB);
            wmma::load_matrix_sync(bl, sWl + k * 16 * LDB + cc, LDB);
            wmma::mma_sync(acc[c], ah, bh, acc[c]);
            wmma::mma_sync(acc[c], ah, bl, acc[c]);
            wmma::mma_sync(acc[c], al, bh, acc[c]);
        }
    }
    __syncthreads();
    #pragma unroll
    for (int c = 0; c < 4; c++)
        wmma::store_matrix_sync(sC + wr * 16 * LDC + wc * 64 + c * 16, acc[c],
                                LDC, wmma::mem_row_major);
    __syncthreads();

    for (int i = tid; i < BLK_ROWS * 32; i += 256) {
        int r = i >> 5, c4 = i & 31;
        int grow = block_row + r;
        if (grow < N_NODES) {
            float4 cv = ((const float4*)(sC + r * LDC))[c4];
            float4 bv = ((const float4*)bias)[c4];
            __half2* p = (__half2*)(g_h1h + (size_t)grow * D);
            p[c4 * 2]     = __floats2half2_rn(cv.x + bv.x, cv.y + bv.y);
            p[c4 * 2 + 1] = __floats2half2_rn(cv.z + bv.z, cv.w + bv.w);
        }
    }
}

// ---------------- dual histogram: edges then batch (one atomic pass) ----------------
__global__ void hist_kernel(const int* __restrict__ rows, const int* __restrict__ x) {
    int i = blockIdx.x * blockDim.x + threadIdx.x;
    if (i < N_EDGES) g_eloc[i] = atomicAdd(&g_cnt[rows[i]], 1);
    int b = i - N_EDGES;
    if (b >= 0 && b < BATCH) {
        int xv = x[b];
        if (xv >= 1 && xv <= N_NODES) g_elocb[b] = atomicAdd(&g_cntb[xv - 1], 1);
        else g_elocb[b] = -1;
    }
}

// ---------------- fused single-pass scan (publish + lookback) ----------------
// Grid (NBLK, 2) = 196 blocks @ 1024 thr -> all resident in wave 1 -> spin is safe.
__global__ void scan_kernel() {
    __shared__ int ws[32];
    __shared__ int sadd;
    int a = blockIdx.y;
    const int* cnt = a ? g_cntb : g_cnt;
    int* rp = a ? g_rowptrb : g_rowptr;
    int* pub = a ? g_pub1 : g_pub0;
    int tid = threadIdx.x;
    int lane = tid & 31, w = tid >> 5;
    int idx = blockIdx.x * SCAN_CHUNK + tid;
    int v = (idx < N_NODES) ? cnt[idx] : 0;
    int inc = v;
    #pragma unroll
    for (int off = 1; off < 32; off <<= 1) {
        int t = __shfl_up_sync(0xffffffffu, inc, off);
        if (lane >= off) inc += t;
    }
    if (lane == 31) ws[w] = inc;
    __syncthreads();
    if (w == 0) {
        int b = ws[lane];
        #pragma unroll
        for (int off = 1; off < 32; off <<= 1) {
            int t = __shfl_up_sync(0xffffffffu, b, off);
            if (lane >= off) b += t;
        }
        ws[lane] = b;
    }
    if (tid == 0) sadd = 0;
    __syncthreads();
    int total_prefix = inc + (w ? ws[w - 1] : 0);
    if (tid == 0) atomicExch(&pub[blockIdx.x], ws[31]);   // publish block total

    // lookback: thread t < blockIdx.x spins on predecessor t's total
    int add = 0;
    if (tid < blockIdx.x) {
        volatile int* p = (volatile int*)&pub[tid];
        int pv;
        do { pv = *p; } while (pv < 0);
        add = pv;
    }
    #pragma unroll
    for (int off = 16; off; off >>= 1) add += __shfl_xor_sync(0xffffffffu, add, off);
    if (lane == 0 && add) atomicAdd(&sadd, add);
    __syncthreads();
    int offset = sadd;
    if (idx < N_NODES) rp[idx + 1] = total_prefix + offset;
    if (idx == 0) rp[0] = 0;
}

// ---------------- fused scatter: edges + batch ids (+ zero invalid out rows) ----------
__global__ void scatter_kernel(const float* __restrict__ vals,
                               const int* __restrict__ rows,
                               const int* __restrict__ cols,
                               const int* __restrict__ x,
                               float* __restrict__ out) {
    int i = blockIdx.x * blockDim.x + threadIdx.x;
    if (i < N_EDGES) {
        int p = g_rowptr[rows[i]] + g_eloc[i];
        g_epack[p] = make_int2(cols[i], __float_as_int(vals[i]));
    }
    int b = i - N_EDGES;
    if (b >= 0 && b < BATCH) {
        int xv = x[b];
        if (xv >= 1 && xv <= N_NODES) {
            g_bidx[g_rowptrb[xv - 1] + g_elocb[b]] = b;
        } else {
            float4* o = (float4*)(out + (size_t)b * D);
            #pragma unroll
            for (int k = 0; k < 32; k++) o[k] = make_float4(0.f, 0.f, 0.f, 0.f);
        }
    }
}

// ---------------- fused SpMM + ReLU + LayerNorm + direct batch scatter ----------------
// R13 config: 256 threads, 8 rows/CTA, uint2 gathers, 8-wide unroll.
__global__ void spmm_ln_kernel(const float* __restrict__ gamma,
                               const float* __restrict__ beta,
                               float* __restrict__ out) {
    int row = blockIdx.x * 8 + (threadIdx.x >> 5);
    if (row >= N_NODES) return;
    int lane = threadIdx.x & 31;
    int s = g_rowptr[row];
    int e = g_rowptr[row + 1];

    float4 acc = make_float4(0.f, 0.f, 0.f, 0.f);
    for (int base = s; base < e; base += 32) {
        int n = min(32, e - base);
        int2 ev = make_int2(0, 0);
        if (base + lane < e) ev = g_epack[base + lane];
        int j = 0;
        for (; j + 8 <= n; j += 8) {
            float v[8]; uint2 m[8];
            #pragma unroll
            for (int u = 0; u < 8; u++) {
                int c = __shfl_sync(0xffffffffu, ev.x, j + u);
                v[u] = __int_as_float(__shfl_sync(0xffffffffu, ev.y, j + u));
                m[u] = ((const uint2*)(g_h1h + (size_t)c * D))[lane];
            }
            #pragma unroll
            for (int u = 0; u < 8; u++) {
                float2 f0 = __half22float2(*(__half2*)&m[u].x);
                float2 f1 = __half22float2(*(__half2*)&m[u].y);
                acc.x = fmaf(v[u], f0.x, acc.x);
                acc.y = fmaf(v[u], f0.y, acc.y);
                acc.z = fmaf(v[u], f1.x, acc.z);
                acc.w = fmaf(v[u], f1.y, acc.w);
            }
        }
        for (; j < n; j++) {
            int   c = __shfl_sync(0xffffffffu, ev.x, j);
            float v = __int_as_float(__shfl_sync(0xffffffffu, ev.y, j));
            uint2 m = ((const uint2*)(g_h1h + (size_t)c * D))[lane];
            float2 f0 = __half22float2(*(__half2*)&m.x);
            float2 f1 = __half22float2(*(__half2*)&m.y);
            acc.x = fmaf(v, f0.x, acc.x);
            acc.y = fmaf(v, f0.y, acc.y);
            acc.z = fmaf(v, f1.x, acc.z);
            acc.w = fmaf(v, f1.y, acc.w);
        }
    }

    acc.x = fmaxf(acc.x, 0.f); acc.y = fmaxf(acc.y, 0.f);
    acc.z = fmaxf(acc.z, 0.f); acc.w = fmaxf(acc.w, 0.f);

    float sm = acc.x + acc.y + acc.z + acc.w;
    #pragma unroll
    for (int o = 16; o; o >>= 1) sm += __shfl_xor_sync(0xffffffffu, sm, o);
    float mu = sm * (1.f / 128.f);

    float dx = acc.x - mu, dy = acc.y - mu, dz = acc.z - mu, dw = acc.w - mu;
    float q = dx * dx + dy * dy + dz * dz + dw * dw;
    #pragma unroll
    for (int o = 16; o; o >>= 1) q += __shfl_xor_sync(0xffffffffu, q, o);
    float rs = rsqrtf(q * (1.f / 128.f) + LN_EPS);

    float4 g = ((const float4*)gamma)[lane];
    float4 b = ((const float4*)beta)[lane];
    float4 o;
    o.x = dx * rs * g.x + b.x;
    o.y = dy * rs * g.y + b.y;
    o.z = dz * rs * g.z + b.z;
    o.w = dw * rs * g.w + b.w;

    int sb = g_rowptrb[row];
    int eb = g_rowptrb[row + 1];
    for (int t = sb; t < eb; t++) {
        int b2 = g_bidx[t];
        __stcs((float4*)(out + (size_t)b2 * D) + lane, o);
    }
}

extern "C" void kernel_launch(void* const* d_in, const int* in_sizes, int n_in,
                              void* d_out, int out_size) {
    const int*   x     = (const int*)d_in[0];
    const float* emb   = (const float*)d_in[1];
    const float* W     = (const float*)d_in[2];
    const float* bias  = (const float*)d_in[3];
    const float* vals  = (const float*)d_in[4];
    const int*   rows  = (const int*)d_in[5];
    const int*   cols  = (const int*)d_in[6];
    const float* gamma = (const float*)d_in[7];
    const float* beta  = (const float*)d_in[8];
    float* out = (float*)d_out;

    static cudaStream_t s2 = nullptr;
    static cudaEvent_t evFork = nullptr, evJoin = nullptr;
    if (s2 == nullptr) {
        cudaStreamCreateWithFlags(&s2, cudaStreamNonBlocking);
        cudaEventCreateWithFlags(&evFork, cudaEventDisableTiming);
        cudaEventCreateWithFlags(&evJoin, cudaEventDisableTiming);
    }

    cudaFuncSetAttribute(gemm_kernel, cudaFuncAttributeMaxDynamicSharedMemorySize, GEMM_SMEM);

    // init feeds both branches (W for gemm, zeroed counters + scan flags for CSR)
    init_kernel<<<(N_NODES + 255) / 256, 256>>>(W);

    // fork: CSR chain on s2 overlaps GEMM on the main stream
    cudaEventRecord(evFork, 0);
    cudaStreamWaitEvent(s2, evFork, 0);

    hist_kernel<<<(N_EDGES + BATCH + 255) / 256, 256, 0, s2>>>(rows, x);
    scan_kernel<<<dim3(NBLK, 2), SCAN_CHUNK, 0, s2>>>();
    scatter_kernel<<<(N_EDGES + BATCH + 255) / 256, 256, 0, s2>>>(vals, rows, cols, x, out);

    gemm_kernel<<<(N_NODES + BLK_ROWS - 1) / BLK_ROWS, 256, GEMM_SMEM>>>(emb, bias);

    // join
    cudaEventRecord(evJoin, s2);
    cudaStreamWaitEvent(0, evJoin, 0);

    spmm_ln_kernel<<<(N_NODES + 7) / 8, 256>>>(gamma, beta, out);
}

// round 17
// speedup vs baseline: 1.0574x; 1.0125x over previous
#include <cuda_runtime.h>
#include <cuda_bf16.h>
#include <cuda_fp16.h>
#include <mma.h>

#define N_NODES 100000
#define D 128
#define N_EDGES 1600000
#define BATCH 500000
#define LN_EPS 1e-5f
#define SCAN_CHUNK 1024
#define NBLK ((N_NODES + SCAN_CHUNK - 1) / SCAN_CHUNK)   // 98

using namespace nvcuda;

// Scratch (device globals; no allocation allowed)
__device__ __align__(128) __half g_h1h[N_NODES * D]; // GEMM output (fp16)
__device__ __align__(128) int2  g_epack[N_EDGES];    // CSR-permuted {col, val}
__device__ int g_eloc[N_EDGES];
__device__ int g_elocb[BATCH];
__device__ int g_bidx[BATCH];                        // batch ids grouped by node
__device__ int g_cnt[N_NODES];
__device__ int g_cntb[N_NODES];
__device__ int g_rowptr[N_NODES + 1];
__device__ int g_rowptrb[N_NODES + 1];
__device__ int g_pub0[NBLK];                         // published block totals (-1 = empty)
__device__ int g_pub1[NBLK];
__device__ __align__(128) __nv_bfloat16 g_Wh[D * D];
__device__ __align__(128) __nv_bfloat16 g_Wl[D * D];

#define LDA 136
#define LDB 136
#define LDC 132
#define BLK_ROWS 64
#define GEMM_SMEM (128 * LDB * 2 * 2 + BLK_ROWS * LDA * 2 * 2)   // 104448

// ---------------- init: W hi/lo pre-conversion + zero counters + scan flags ----------
__global__ void init_kernel(const float* __restrict__ W) {
    int i = blockIdx.x * blockDim.x + threadIdx.x;
    if (i < D * D) {
        float wv = W[i];
        __nv_bfloat16 whi = __float2bfloat16(wv);
        g_Wh[i] = whi;
        g_Wl[i] = __float2bfloat16(wv - __bfloat162float(whi));
    }
    if (i < N_NODES) { g_cnt[i] = 0; g_cntb[i] = 0; }
    if (i < NBLK) { g_pub0[i] = -1; g_pub1[i] = -1; }
}

// ---------------- GEMM: h1 = emb @ W + bias (bf16 hi/lo, fp32 accum, fp16 store) ------
__global__ void gemm_kernel(const float* __restrict__ emb,
                            const float* __restrict__ bias) {
    extern __shared__ __nv_bfloat16 smem[];
    __nv_bfloat16* sWh = smem;
    __nv_bfloat16* sWl = sWh + 128 * LDB;
    __nv_bfloat16* sAh = sWl + 128 * LDB;
    __nv_bfloat16* sAl = sAh + BLK_ROWS * LDA;
    float* sC = (float*)sAh;

    int tid = threadIdx.x;
    int wid = tid >> 5;
    int wr = wid >> 1;
    int wc = wid & 1;
    int block_row = blockIdx.x * BLK_ROWS;

    for (int i = tid; i < 128 * 16; i += 256) {
        int r = i >> 4, q = i & 15;
        ((uint4*)(sWh + r * LDB))[q] = ((const uint4*)(g_Wh + r * D))[q];
        ((uint4*)(sWl + r * LDB))[q] = ((const uint4*)(g_Wl + r * D))[q];
    }
    for (int i = tid; i < BLK_ROWS * 32; i += 256) {
        int r = i >> 5, c4 = i & 31;
        int grow = block_row + r;
        float4 a = make_float4(0.f, 0.f, 0.f, 0.f);
        if (grow < N_NODES) a = ((const float4*)(emb + (size_t)grow * D))[c4];
        __nv_bfloat16 h0 = __float2bfloat16(a.x), h1 = __float2bfloat16(a.y);
        __nv_bfloat16 h2 = __float2bfloat16(a.z), h3 = __float2bfloat16(a.w);
        __nv_bfloat16 l0 = __float2bfloat16(a.x - __bfloat162float(h0));
        __nv_bfloat16 l1 = __float2bfloat16(a.y - __bfloat162float(h1));
        __nv_bfloat16 l2 = __float2bfloat16(a.z - __bfloat162float(h2));
        __nv_bfloat16 l3 = __float2bfloat16(a.w - __bfloat162float(h3));
        __nv_bfloat162* ph = (__nv_bfloat162*)(sAh + r * LDA);
        __nv_bfloat162* pl = (__nv_bfloat162*)(sAl + r * LDA);
        ph[c4 * 2]     = __nv_bfloat162(h0, h1);
        ph[c4 * 2 + 1] = __nv_bfloat162(h2, h3);
        pl[c4 * 2]     = __nv_bfloat162(l0, l1);
        pl[c4 * 2 + 1] = __nv_bfloat162(l2, l3);
    }
    __syncthreads();

    wmma::fragment<wmma::accumulator, 16, 16, 16, float> acc[4];
    #pragma unroll
    for (int c = 0; c < 4; c++) wmma::fill_fragment(acc[c], 0.f);

    #pragma unroll
    for (int k = 0; k < 8; k++) {
        wmma::fragment<wmma::matrix_a, 16, 16, 16, __nv_bfloat16, wmma::row_major> ah, al;
        wmma::load_matrix_sync(ah, sAh + wr * 16 * LDA + k * 16, LDA);
        wmma::load_matrix_sync(al, sAl + wr * 16 * LDA + k * 16, LDA);
        #pragma unroll
        for (int c = 0; c < 4; c++) {
            int cc = wc * 64 + c * 16;
            wmma::fragment<wmma::matrix_b, 16, 16, 16, __nv_bfloat16, wmma::row_major> bh, bl;
            wmma::load_matrix_sync(bh, sWh + k * 16 * LDB + cc, LDB);
            wmma::load_matrix_sync(bl, sWl + k * 16 * LDB + cc, LDB);
            wmma::mma_sync(acc[c], ah, bh, acc[c]);
            wmma::mma_sync(acc[c], ah, bl, acc[c]);
            wmma::mma_sync(acc[c], al, bh, acc[c]);
        }
    }
    __syncthreads();
    #pragma unroll
    for (int c = 0; c < 4; c++)
        wmma::store_matrix_sync(sC + wr * 16 * LDC + wc * 64 + c * 16, acc[c],
                                LDC, wmma::mem_row_major);
    __syncthreads();

    for (int i = tid; i < BLK_ROWS * 32; i += 256) {
        int r = i >> 5, c4 = i & 31;
        int grow = block_row + r;
        if (grow < N_NODES) {
            float4 cv = ((const float4*)(sC + r * LDC))[c4];
            float4 bv = ((const float4*)bias)[c4];
            __half2* p = (__half2*)(g_h1h + (size_t)grow * D);
            p[c4 * 2]     = __floats2half2_rn(cv.x + bv.x, cv.y + bv.y);
            p[c4 * 2 + 1] = __floats2half2_rn(cv.z + bv.z, cv.w + bv.w);
        }
    }
}

// ---------------- dual histogram: edges then batch (one atomic pass) ----------------
__global__ void hist_kernel(const int* __restrict__ rows, const int* __restrict__ x) {
    int i = blockIdx.x * blockDim.x + threadIdx.x;
    if (i < N_EDGES) g_eloc[i] = atomicAdd(&g_cnt[rows[i]], 1);
    int b = i - N_EDGES;
    if (b >= 0 && b < BATCH) {
        int xv = x[b];
        if (xv >= 1 && xv <= N_NODES) g_elocb[b] = atomicAdd(&g_cntb[xv - 1], 1);
        else g_elocb[b] = -1;
    }
}

// ---------------- fused single-pass scan (publish + lookback) ----------------
// Grid (NBLK, 2) = 196 blocks @ 1024 thr -> all resident in wave 1 -> spin is safe.
__global__ void scan_kernel() {
    __shared__ int ws[32];
    __shared__ int sadd;
    int a = blockIdx.y;
    const int* cnt = a ? g_cntb : g_cnt;
    int* rp = a ? g_rowptrb : g_rowptr;
    int* pub = a ? g_pub1 : g_pub0;
    int tid = threadIdx.x;
    int lane = tid & 31, w = tid >> 5;
    int idx = blockIdx.x * SCAN_CHUNK + tid;
    int v = (idx < N_NODES) ? cnt[idx] : 0;
    int inc = v;
    #pragma unroll
    for (int off = 1; off < 32; off <<= 1) {
        int t = __shfl_up_sync(0xffffffffu, inc, off);
        if (lane >= off) inc += t;
    }
    if (lane == 31) ws[w] = inc;
    __syncthreads();
    if (w == 0) {
        int b = ws[lane];
        #pragma unroll
        for (int off = 1; off < 32; off <<= 1) {
            int t = __shfl_up_sync(0xffffffffu, b, off);
            if (lane >= off) b += t;
        }
        ws[lane] = b;
    }
    if (tid == 0) sadd = 0;
    __syncthreads();
    int total_prefix = inc + (w ? ws[w - 1] : 0);
    if (tid == 0) atomicExch(&pub[blockIdx.x], ws[31]);   // publish block total

    // lookback: thread t < blockIdx.x spins on predecessor t's total
    int add = 0;
    if (tid < blockIdx.x) {
        volatile int* p = (volatile int*)&pub[tid];
        int pv;
        do { pv = *p; } while (pv < 0);
        add = pv;
    }
    #pragma unroll
    for (int off = 16; off; off >>= 1) add += __shfl_xor_sync(0xffffffffu, add, off);
    if (lane == 0 && add) atomicAdd(&sadd, add);
    __syncthreads();
    int offset = sadd;
    if (idx < N_NODES) rp[idx + 1] = total_prefix + offset;
    if (idx == 0) rp[0] = 0;
}

// ---------------- fused scatter: edges + batch ids (+ zero invalid out rows) ----------
__global__ void scatter_kernel(const float* __restrict__ vals,
                               const int* __restrict__ rows,
                               const int* __restrict__ cols,
                               const int* __restrict__ x,
                               float* __restrict__ out) {
    int i = blockIdx.x * blockDim.x + threadIdx.x;
    if (i < N_EDGES) {
        int p = g_rowptr[rows[i]] + g_eloc[i];
        g_epack[p] = make_int2(cols[i], __float_as_int(vals[i]));
    }
    int b = i - N_EDGES;
    if (b >= 0 && b < BATCH) {
        int xv = x[b];
        if (xv >= 1 && xv <= N_NODES) {
            g_bidx[g_rowptrb[xv - 1] + g_elocb[b]] = b;
        } else {
            float4* o = (float4*)(out + (size_t)b * D);
            #pragma unroll
            for (int k = 0; k < 32; k++) o[k] = make_float4(0.f, 0.f, 0.f, 0.f);
        }
    }
}

// ---------------- fused SpMM + ReLU + LayerNorm + direct batch scatter ----------------
// R13 gather config; output target indices now staged coalesced + shfl-broadcast
// (kills the serial dependent-load chain in the scatter tail).
__global__ void spmm_ln_kernel(const float* __restrict__ gamma,
                               const float* __restrict__ beta,
                               float* __restrict__ out) {
    int row = blockIdx.x * 8 + (threadIdx.x >> 5);
    if (row >= N_NODES) return;
    int lane = threadIdx.x & 31;
    int s = g_rowptr[row];
    int e = g_rowptr[row + 1];

    float4 acc = make_float4(0.f, 0.f, 0.f, 0.f);
    for (int base = s; base < e; base += 32) {
        int n = min(32, e - base);
        int2 ev = make_int2(0, 0);
        if (base + lane < e) ev = g_epack[base + lane];
        int j = 0;
        for (; j + 8 <= n; j += 8) {
            float v[8]; uint2 m[8];
            #pragma unroll
            for (int u = 0; u < 8; u++) {
                int c = __shfl_sync(0xffffffffu, ev.x, j + u);
                v[u] = __int_as_float(__shfl_sync(0xffffffffu, ev.y, j + u));
                m[u] = ((const uint2*)(g_h1h + (size_t)c * D))[lane];
            }
            #pragma unroll
            for (int u = 0; u < 8; u++) {
                float2 f0 = __half22float2(*(__half2*)&m[u].x);
                float2 f1 = __half22float2(*(__half2*)&m[u].y);
                acc.x = fmaf(v[u], f0.x, acc.x);
                acc.y = fmaf(v[u], f0.y, acc.y);
                acc.z = fmaf(v[u], f1.x, acc.z);
                acc.w = fmaf(v[u], f1.y, acc.w);
            }
        }
        for (; j < n; j++) {
            int   c = __shfl_sync(0xffffffffu, ev.x, j);
            float v = __int_as_float(__shfl_sync(0xffffffffu, ev.y, j));
            uint2 m = ((const uint2*)(g_h1h + (size_t)c * D))[lane];
            float2 f0 = __half22float2(*(__half2*)&m.x);
            float2 f1 = __half22float2(*(__half2*)&m.y);
            acc.x = fmaf(v, f0.x, acc.x);
            acc.y = fmaf(v, f0.y, acc.y);
            acc.z = fmaf(v, f1.x, acc.z);
            acc.w = fmaf(v, f1.y, acc.w);
        }
    }

    acc.x = fmaxf(acc.x, 0.f); acc.y = fmaxf(acc.y, 0.f);
    acc.z = fmaxf(acc.z, 0.f); acc.w = fmaxf(acc.w, 0.f);

    float sm = acc.x + acc.y + acc.z + acc.w;
    #pragma unroll
    for (int o = 16; o; o >>= 1) sm += __shfl_xor_sync(0xffffffffu, sm, o);
    float mu = sm * (1.f / 128.f);

    float dx = acc.x - mu, dy = acc.y - mu, dz = acc.z - mu, dw = acc.w - mu;
    float q = dx * dx + dy * dy + dz * dz + dw * dw;
    #pragma unroll
    for (int o = 16; o; o >>= 1) q += __shfl_xor_sync(0xffffffffu, q, o);
    float rs = rsqrtf(q * (1.f / 128.f) + LN_EPS);

    float4 g = ((const float4*)gamma)[lane];
    float4 b = ((const float4*)beta)[lane];
    float4 o;
    o.x = dx * rs * g.x + b.x;
    o.y = dy * rs * g.y + b.y;
    o.z = dz * rs * g.z + b.z;
    o.w = dw * rs * g.w + b.w;

    // direct scatter: stage up to 32 target indices with ONE coalesced load,
    // broadcast via shfl, then issue independent streaming stores.
    int sb = g_rowptrb[row];
    int eb = g_rowptrb[row + 1];
    for (int tb = sb; tb < eb; tb += 32) {
        int nt = min(32, eb - tb);
        int bid = (tb + lane < eb) ? g_bidx[tb + lane] : 0;
        for (int t = 0; t < nt; t++) {
            int b2 = __shfl_sync(0xffffffffu, bid, t);
            __stcs((float4*)(out + (size_t)b2 * D) + lane, o);
        }
    }
}

extern "C" void kernel_launch(void* const* d_in, const int* in_sizes, int n_in,
                              void* d_out, int out_size) {
    const int*   x     = (const int*)d_in[0];
    const float* emb   = (const float*)d_in[1];
    const float* W     = (const float*)d_in[2];
    const float* bias  = (const float*)d_in[3];
    const float* vals  = (const float*)d_in[4];
    const int*   rows  = (const int*)d_in[5];
    const int*   cols  = (const int*)d_in[6];
    const float* gamma = (const float*)d_in[7];
    const float* beta  = (const float*)d_in[8];
    float* out = (float*)d_out;

    static cudaStream_t s2 = nullptr;
    static cudaEvent_t evFork = nullptr, evJoin = nullptr;
    if (s2 == nullptr) {
        cudaStreamCreateWithFlags(&s2, cudaStreamNonBlocking);
        cudaEventCreateWithFlags(&evFork, cudaEventDisableTiming);
        cudaEventCreateWithFlags(&evJoin, cudaEventDisableTiming);
    }

    cudaFuncSetAttribute(gemm_kernel, cudaFuncAttributeMaxDynamicSharedMemorySize, GEMM_SMEM);

    // init feeds both branches (W for gemm, zeroed counters + scan flags for CSR)
    init_kernel<<<(N_NODES + 255) / 256, 256>>>(W);

    // fork: CSR chain on s2 overlaps GEMM on the main stream
    cudaEventRecord(evFork, 0);
    cudaStreamWaitEvent(s2, evFork, 0);

    hist_kernel<<<(N_EDGES + BATCH + 255) / 256, 256, 0, s2>>>(rows, x);
    scan_kernel<<<dim3(NBLK, 2), SCAN_CHUNK, 0, s2>>>();
    scatter_kernel<<<(N_EDGES + BATCH + 255) / 256, 256, 0, s2>>>(vals, rows, cols, x, out);

    gemm_kernel<<<(N_NODES + BLK_ROWS - 1) / BLK_ROWS, 256, GEMM_SMEM>>>(emb, bias);

    // join
    cudaEventRecord(evJoin, s2);
    cudaStreamWaitEvent(0, evJoin, 0);

    spmm_ln_kernel<<<(N_NODES + 7) / 8, 256>>>(gamma, beta, out);
}